// round 2
// baseline (speedup 1.0000x reference)
#include <cuda_runtime.h>
#include <cuda_bf16.h>

#define N_TOKENS 12288
#define DHEAD    128
#define NUM_BATCH 32
#define BM 64
#define BN 64
#define DS (DHEAD + 4)   // 132 floats per smem row (pad for bank conflicts)
#define PS (BN + 4)      // 68

__device__ int g_seg_start[NUM_BATCH + 1];

// ---------------------------------------------------------------------------
// Pre-kernel: segment offsets from sorted batch_seg (histogram + tiny scan)
// ---------------------------------------------------------------------------
__global__ void seg_offsets_kernel(const int* __restrict__ batch_seg, int n) {
    __shared__ int cnt[NUM_BATCH];
    int tid = threadIdx.x;
    if (tid < NUM_BATCH) cnt[tid] = 0;
    __syncthreads();
    for (int i = tid; i < n; i += blockDim.x)
        atomicAdd(&cnt[batch_seg[i]], 1);
    __syncthreads();
    if (tid == 0) {
        int run = 0;
        for (int b = 0; b < NUM_BATCH; b++) { g_seg_start[b] = run; run += cnt[b]; }
        g_seg_start[NUM_BATCH] = run;
    }
}

// ---------------------------------------------------------------------------
// Main kernel: segment-masked flash attention, fp32
// Block: 256 threads = 16(ty) x 16(tx). Each thread: 4 rows x 4 score cols,
// output 4 rows x 8 d-cols (cols tx*4..+3 and 64+tx*4..+3).
// ---------------------------------------------------------------------------
__global__ __launch_bounds__(256, 1)
void attn_kernel(const float* __restrict__ Q, const float* __restrict__ K,
                 const float* __restrict__ V, const int* __restrict__ bseg,
                 float* __restrict__ out) {
    extern __shared__ float sm[];
    float* Qs = sm;                    // [BM][DS]
    float* Ks = Qs + BM * DS;          // [BN][DS]
    float* Vs = Ks + BN * DS;          // [BN][DS]
    float* Psm = Vs + BN * DS;         // [BM][PS]
    __shared__ int row_lo[BM], row_hi[BM];

    const int i0  = blockIdx.x * BM;
    const int tid = threadIdx.x;
    const int ty  = tid >> 4;          // 0..15
    const int tx  = tid & 15;          // 0..15

    // Load Q tile (coalesced float4)
    #pragma unroll
    for (int t = tid; t < BM * (DHEAD / 4); t += 256) {
        int r  = t >> 5;               // /32
        int c4 = t & 31;
        float4 v = ((const float4*)(Q + (size_t)(i0 + r) * DHEAD))[c4];
        *(float4*)&Qs[r * DS + c4 * 4] = v;
    }
    if (tid < BM) {
        int b = bseg[i0 + tid];
        row_lo[tid] = g_seg_start[b];
        row_hi[tid] = g_seg_start[b + 1];
    }
    __syncthreads();

    const int kstart = row_lo[0];
    const int kend   = row_hi[BM - 1];

    int rlo[4], rhi[4];
    float m_r[4], l_r[4];
    float o_acc[4][8];
    #pragma unroll
    for (int i = 0; i < 4; i++) {
        rlo[i] = row_lo[ty * 4 + i];
        rhi[i] = row_hi[ty * 4 + i];
        m_r[i] = -1e30f;
        l_r[i] = 0.f;
        #pragma unroll
        for (int dcc = 0; dcc < 8; dcc++) o_acc[i][dcc] = 0.f;
    }

    const float isd = 0.0883883476483184f;  // 1/sqrt(128)

    for (int kt = kstart; kt < kend; kt += BN) {
        __syncthreads();  // previous iteration's Vs/Ps reads complete
        // Load K,V tiles (clamp OOB index; masking handles correctness)
        #pragma unroll
        for (int t = tid; t < BN * (DHEAD / 4); t += 256) {
            int r  = t >> 5;
            int c4 = t & 31;
            int j  = kt + r; if (j >= N_TOKENS) j = N_TOKENS - 1;
            *(float4*)&Ks[r * DS + c4 * 4] = ((const float4*)(K + (size_t)j * DHEAD))[c4];
            *(float4*)&Vs[r * DS + c4 * 4] = ((const float4*)(V + (size_t)j * DHEAD))[c4];
        }
        __syncthreads();

        // ---- Scores: s[4][4] = Q(4 rows) . K(4 cols) over D ----
        float s[4][4];
        #pragma unroll
        for (int i = 0; i < 4; i++)
            #pragma unroll
            for (int j = 0; j < 4; j++) s[i][j] = 0.f;

        #pragma unroll 8
        for (int d4 = 0; d4 < DHEAD / 4; d4++) {
            float4 q[4], k[4];
            #pragma unroll
            for (int i = 0; i < 4; i++)
                q[i] = *(const float4*)&Qs[(ty * 4 + i) * DS + d4 * 4];
            #pragma unroll
            for (int j = 0; j < 4; j++)
                k[j] = *(const float4*)&Ks[(tx * 4 + j) * DS + d4 * 4];
            #pragma unroll
            for (int i = 0; i < 4; i++)
                #pragma unroll
                for (int j = 0; j < 4; j++) {
                    s[i][j] += q[i].x * k[j].x;
                    s[i][j] += q[i].y * k[j].y;
                    s[i][j] += q[i].z * k[j].z;
                    s[i][j] += q[i].w * k[j].w;
                }
        }

        // ---- Mask + online softmax update ----
        #pragma unroll
        for (int i = 0; i < 4; i++) {
            bool ok[4];
            float tm = -1e30f;
            #pragma unroll
            for (int j = 0; j < 4; j++) {
                int col = kt + tx * 4 + j;
                ok[j] = (col >= rlo[i]) && (col < rhi[i]);
                if (ok[j]) tm = fmaxf(tm, s[i][j]);
            }
            // reduce max over 16 tx lanes (within half-warp)
            #pragma unroll
            for (int o = 8; o >= 1; o >>= 1)
                tm = fmaxf(tm, __shfl_xor_sync(0xffffffffu, tm, o));
            float mnew  = fmaxf(m_r[i], tm);
            float alpha = __expf((m_r[i] - mnew) * isd);

            float e[4];
            float rs = 0.f;
            #pragma unroll
            for (int j = 0; j < 4; j++) {
                e[j] = ok[j] ? __expf((s[i][j] - mnew) * isd) : 0.f;
                rs += e[j];
            }
            #pragma unroll
            for (int o = 8; o >= 1; o >>= 1)
                rs += __shfl_xor_sync(0xffffffffu, rs, o);

            l_r[i] = l_r[i] * alpha + rs;
            m_r[i] = mnew;
            #pragma unroll
            for (int dcc = 0; dcc < 8; dcc++) o_acc[i][dcc] *= alpha;

            float4 ev = make_float4(e[0], e[1], e[2], e[3]);
            *(float4*)&Psm[(ty * 4 + i) * PS + tx * 4] = ev;
        }
        __syncthreads();

        // ---- O += P @ V ----
        #pragma unroll 4
        for (int c = 0; c < BN; c++) {
            float4 v0 = *(const float4*)&Vs[c * DS + tx * 4];
            float4 v1 = *(const float4*)&Vs[c * DS + 64 + tx * 4];
            #pragma unroll
            for (int i = 0; i < 4; i++) {
                float p = Psm[(ty * 4 + i) * PS + c];
                o_acc[i][0] += p * v0.x;
                o_acc[i][1] += p * v0.y;
                o_acc[i][2] += p * v0.z;
                o_acc[i][3] += p * v0.w;
                o_acc[i][4] += p * v1.x;
                o_acc[i][5] += p * v1.y;
                o_acc[i][6] += p * v1.z;
                o_acc[i][7] += p * v1.w;
            }
        }
    }

    // ---- Epilogue: normalize and store ----
    #pragma unroll
    for (int i = 0; i < 4; i++) {
        float inv = 1.0f / l_r[i];   // EPS contribution < 1e-6 relative (see analysis)
        size_t r = (size_t)(i0 + ty * 4 + i);
        float4 a = make_float4(o_acc[i][0] * inv, o_acc[i][1] * inv,
                               o_acc[i][2] * inv, o_acc[i][3] * inv);
        float4 b = make_float4(o_acc[i][4] * inv, o_acc[i][5] * inv,
                               o_acc[i][6] * inv, o_acc[i][7] * inv);
        *(float4*)&out[r * DHEAD + tx * 4]      = a;
        *(float4*)&out[r * DHEAD + 64 + tx * 4] = b;
    }
}

// ---------------------------------------------------------------------------
extern "C" void kernel_launch(void* const* d_in, const int* in_sizes, int n_in,
                              void* d_out, int out_size) {
    const float* Q   = (const float*)d_in[0];
    const float* K   = (const float*)d_in[1];
    const float* V   = (const float*)d_in[2];
    const int* bseg  = (const int*)d_in[n_in - 1];  // batch_seg is last input
    float* out       = (float*)d_out;

    const int smem_bytes = (BM * DS + 2 * BN * DS + BM * PS) * (int)sizeof(float);
    cudaFuncSetAttribute(attn_kernel, cudaFuncAttributeMaxDynamicSharedMemorySize,
                         smem_bytes);

    seg_offsets_kernel<<<1, 1024>>>(bseg, N_TOKENS);
    attn_kernel<<<N_TOKENS / BM, 256, smem_bytes>>>(Q, K, V, bseg, out);
}